// round 1
// baseline (speedup 1.0000x reference)
#include <cuda_runtime.h>
#include <math.h>

#define Bsz 64
#define Ssz 512
#define Hsz 400
#define Dsz 400
#define Vsz 32000
#define Lsz 16
#define G3  1200   // 3*H

// ---------------- scratch (static device globals; no allocation) ----------------
__device__ float g_G[Bsz * 2 * G3];   // [b][0:1200]=gi, [1200:2400]=gh
__device__ float g_h[Bsz * Hsz];      // current hidden state
__device__ float g_x[Bsz * Dsz];      // current input embedding

// ---------------- init: h0 = encoded_hidden[0], x0 = slot_emb[slot] ----------------
__global__ void init_kernel(const float* __restrict__ eh,
                            const float* __restrict__ slot_emb,
                            const int* __restrict__ slot_p) {
    int idx = blockIdx.x * blockDim.x + threadIdx.x;
    if (idx < Bsz * Hsz) {
        g_h[idx] = eh[idx];
        int j = idx % Dsz;
        g_x[idx] = slot_emb[slot_p[0] * Dsz + j];
    }
}

// ---------------- GEMM: G = [x @ W_ih^T + b_ih | h @ W_hh^T + b_hh] ----------------
// Grid 120 blocks: mat = bx/60 (0: gi from x/W_ih, 1: gh from h/W_hh), jtile = bx%60 (20 rows).
// Block 320 threads; thread computes a 2(b) x 2(j) micro-tile over K=400.
#define JT 20
#define KT 100
__global__ __launch_bounds__(320) void gemm_kernel(const float* __restrict__ Wih,
                                                   const float* __restrict__ Whh,
                                                   const float* __restrict__ bih,
                                                   const float* __restrict__ bhh) {
    __shared__ float As[64][KT + 2];   // +2 pad (even) keeps float2 alignment
    __shared__ float Ws[JT][KT + 2];

    int bx = blockIdx.x;
    int mat = bx / 60;
    int jbase = (bx % 60) * JT;
    const float* A    = mat ? g_h : g_x;
    const float* W    = mat ? Whh : Wih;
    const float* bias = mat ? bhh : bih;

    int tx = threadIdx.x;
    int tb = tx / 10;          // 0..31 -> b pair
    int tj = tx % 10;          // 0..9  -> j pair
    int b0 = tb * 2;
    int j0 = tj * 2;

    float acc00 = 0.f, acc01 = 0.f, acc10 = 0.f, acc11 = 0.f;

    for (int kt = 0; kt < 400 / KT; kt++) {
        int kb = kt * KT;
        // load A tile: 64 x 100 floats = 1600 float4, 5 per thread
        for (int i = tx; i < 1600; i += 320) {
            int row = i / 25, c4 = i % 25;
            float4 v = *(const float4*)&A[row * 400 + kb + c4 * 4];
            float* dst = &As[row][c4 * 4];
            dst[0] = v.x; dst[1] = v.y; dst[2] = v.z; dst[3] = v.w;
        }
        // load W tile: 20 x 100 floats = 500 float4
        for (int i = tx; i < 500; i += 320) {
            int row = i / 25, c4 = i % 25;
            float4 v = *(const float4*)&W[(jbase + row) * 400 + kb + c4 * 4];
            float* dst = &Ws[row][c4 * 4];
            dst[0] = v.x; dst[1] = v.y; dst[2] = v.z; dst[3] = v.w;
        }
        __syncthreads();
        #pragma unroll 10
        for (int k = 0; k < KT; k += 2) {
            float2 a0 = *(float2*)&As[b0][k];
            float2 a1 = *(float2*)&As[b0 + 1][k];
            float2 w0 = *(float2*)&Ws[j0][k];
            float2 w1 = *(float2*)&Ws[j0 + 1][k];
            acc00 += a0.x * w0.x; acc00 += a0.y * w0.y;
            acc01 += a0.x * w1.x; acc01 += a0.y * w1.y;
            acc10 += a1.x * w0.x; acc10 += a1.y * w0.y;
            acc11 += a1.x * w1.x; acc11 += a1.y * w1.y;
        }
        __syncthreads();
    }

    int gout = mat * G3 + jbase;
    float bj0 = bias[jbase + j0];
    float bj1 = bias[jbase + j0 + 1];
    g_G[(b0    ) * 2400 + gout + j0    ] = acc00 + bj0;
    g_G[(b0    ) * 2400 + gout + j0 + 1] = acc01 + bj1;
    g_G[(b0 + 1) * 2400 + gout + j0    ] = acc10 + bj0;
    g_G[(b0 + 1) * 2400 + gout + j0 + 1] = acc11 + bj1;
}

// ---------------- fused: gates -> h_new -> masked scores -> softmax/argmax ->
//                  scatter into out -> pred -> next x embedding gather ----------------
__global__ __launch_bounds__(512) void attn_kernel(const float* __restrict__ enc,
                                                   const int* __restrict__ lens,
                                                   const int* __restrict__ uttrs,
                                                   const int* __restrict__ targets,
                                                   const int* __restrict__ use_tf_p,
                                                   const float* __restrict__ embedding,
                                                   float* __restrict__ out,
                                                   int t, int write_preds) {
    __shared__ float sh_h[Hsz];
    __shared__ float sc[Ssz];
    __shared__ float redv[512];
    __shared__ int   redi[512];
    __shared__ int   sh_nxt;

    int b = blockIdx.x;
    int tx = threadIdx.x;

    // ---- GRU gates (PyTorch cell math) ----
    if (tx < Hsz) {
        const float* Gb = &g_G[b * 2400];
        float ir = Gb[tx], iz = Gb[400 + tx], in_ = Gb[800 + tx];
        float hr = Gb[1200 + tx], hz = Gb[1600 + tx], hn = Gb[2000 + tx];
        float r = 1.f / (1.f + expf(-(ir + hr)));
        float z = 1.f / (1.f + expf(-(iz + hz)));
        float n = tanhf(in_ + r * hn);
        float hprev = g_h[b * Hsz + tx];
        float hnew = (1.f - z) * n + z * hprev;
        sh_h[tx] = hnew;
        g_h[b * Hsz + tx] = hnew;
    }
    __syncthreads();

    // ---- masked dot-product scores over encoder outputs ----
    int len = lens[b];
    int w = tx >> 5, lane = tx & 31;
    const float4* h4 = (const float4*)sh_h;
    for (int i = 0; i < 32; i += 2) {
        int s0 = w * 32 + i;
        int s1 = s0 + 1;
        float acc0 = 0.f, acc1 = 0.f;
        bool v0 = s0 < len, v1 = s1 < len;
        if (v0 || v1) {
            const float4* e0 = (const float4*)&enc[((size_t)b * Ssz + s0) * Hsz];
            const float4* e1 = (const float4*)&enc[((size_t)b * Ssz + s1) * Hsz];
            #pragma unroll 4
            for (int q = lane; q < 100; q += 32) {
                float4 hv = h4[q];
                if (v0) {
                    float4 a = e0[q];
                    acc0 += a.x * hv.x; acc0 += a.y * hv.y;
                    acc0 += a.z * hv.z; acc0 += a.w * hv.w;
                }
                if (v1) {
                    float4 a = e1[q];
                    acc1 += a.x * hv.x; acc1 += a.y * hv.y;
                    acc1 += a.z * hv.z; acc1 += a.w * hv.w;
                }
            }
            #pragma unroll
            for (int off = 16; off; off >>= 1) {
                acc0 += __shfl_xor_sync(0xFFFFFFFFu, acc0, off);
                acc1 += __shfl_xor_sync(0xFFFFFFFFu, acc1, off);
            }
        }
        if (lane == 0) {
            sc[s0] = v0 ? acc0 : -INFINITY;
            sc[s1] = v1 ? acc1 : -INFINITY;
        }
    }
    __syncthreads();

    // ---- max + first-index argmax (jnp.argmax tie semantics) ----
    float myv = sc[tx];
    redv[tx] = myv;
    redi[tx] = tx;
    __syncthreads();
    for (int st = 256; st > 0; st >>= 1) {
        if (tx < st) {
            float v2 = redv[tx + st];
            int   i2 = redi[tx + st];
            if (v2 > redv[tx] || (v2 == redv[tx] && i2 < redi[tx])) {
                redv[tx] = v2;
                redi[tx] = i2;
            }
        }
        __syncthreads();
    }
    float m = redv[0];
    int amax = redi[0];
    __syncthreads();

    // ---- softmax ----
    float e = expf(myv - m);     // exp(-inf - m) = 0 for masked rows
    sc[tx] = e;
    redv[tx] = e;
    __syncthreads();
    for (int st = 256; st > 0; st >>= 1) {
        if (tx < st) redv[tx] += redv[tx + st];
        __syncthreads();
    }
    float sum = redv[0];

    // ---- scatter pointer distribution into out[b, t, :] ----
    if (tx < len) {
        float p = sc[tx] / sum;
        int v = uttrs[b * Ssz + tx];
        atomicAdd(&out[(size_t)b * Lsz * Vsz + (size_t)t * Vsz + v], p);
    }

    // ---- pred + next-input token selection ----
    if (tx == 0) {
        int pred = uttrs[b * Ssz + amax];
        if (write_preds)
            out[(size_t)Bsz * Lsz * Vsz + (size_t)t * Bsz + b] = (float)pred;
        int tf = use_tf_p[0];
        sh_nxt = tf ? targets[b * Lsz + t] : pred;
    }
    __syncthreads();

    // ---- x_{t+1} = embedding[nxt] ----
    if (tx < Dsz) {
        g_x[b * Dsz + tx] = embedding[(size_t)sh_nxt * Dsz + tx];
    }
}

// ---------------- launch ----------------
extern "C" void kernel_launch(void* const* d_in, const int* in_sizes, int n_in,
                              void* d_out, int out_size) {
    const float* eh       = (const float*)d_in[0];   // encoded_hidden (1,B,H)
    const float* enc      = (const float*)d_in[1];   // encoded_outputs (B,S,H)
    const int*   lens     = (const int*)d_in[2];     // encoded_lens (B,)
    const int*   uttrs    = (const int*)d_in[3];     // (B,S)
    const int*   targets  = (const int*)d_in[4];     // (B,L)
    const int*   slot     = (const int*)d_in[5];     // scalar
    const int*   use_tf   = (const int*)d_in[6];     // scalar
    const float* emb      = (const float*)d_in[7];   // (V,D)
    const float* slot_emb = (const float*)d_in[8];   // (NSLOTS,D)
    const float* Wih      = (const float*)d_in[9];   // (3H,D)
    const float* Whh      = (const float*)d_in[10];  // (3H,H)
    const float* bih      = (const float*)d_in[11];
    const float* bhh      = (const float*)d_in[12];
    float* out = (float*)d_out;

    // zero full output (pointer distributions are sparse scatters)
    cudaMemsetAsync(d_out, 0, (size_t)out_size * sizeof(float));

    init_kernel<<<50, 512>>>(eh, slot_emb, slot);

    int write_preds = out_size > Bsz * Lsz * Vsz;
    for (int t = 0; t < Lsz; t++) {
        gemm_kernel<<<120, 320>>>(Wih, Whh, bih, bhh);
        attn_kernel<<<64, 512>>>(enc, lens, uttrs, targets, use_tf, emb, out, t, write_preds);
    }
}

// round 2
// speedup vs baseline: 1.3664x; 1.3664x over previous
#include <cuda_runtime.h>
#include <math.h>

#define Bsz 64
#define Ssz 512
#define Hsz 400
#define Dsz 400
#define Vsz 32000
#define Lsz 16
#define NPART 4          // K split
#define KC   100         // K per part
#define JT   24          // j-tile per block

// ---------------- scratch (device globals; no allocation) ----------------
__device__ float g_Gpart[NPART][Bsz][2400];  // [part][b][0:1200 gi | 1200:2400 gh]
__device__ float g_hA[Bsz * Hsz];
__device__ float g_hB[Bsz * Hsz];
__device__ float g_x[Bsz * Dsz];
__device__ float g_scores[Bsz][Ssz];

// ---------------- f32x2 packed-FMA helpers ----------------
__device__ __forceinline__ unsigned long long pk2(float x, float y) {
    unsigned long long r;
    asm("mov.b64 %0, {%1, %2};" : "=l"(r) : "f"(x), "f"(y));
    return r;
}
__device__ __forceinline__ void ffma2(unsigned long long& d,
                                      unsigned long long a, unsigned long long b) {
    asm("fma.rn.f32x2 %0, %1, %2, %0;" : "+l"(d) : "l"(a), "l"(b));
}
__device__ __forceinline__ float2 up2(unsigned long long v) {
    float2 f;
    asm("mov.b64 {%0, %1}, %2;" : "=f"(f.x), "=f"(f.y) : "l"(v));
    return f;
}

// ---------------- init: h0 = encoded_hidden[0], x0 = slot_emb[slot] ----------------
__global__ void init_kernel(const float* __restrict__ eh,
                            const float* __restrict__ slot_emb,
                            const int* __restrict__ slot_p) {
    int idx = blockIdx.x * blockDim.x + threadIdx.x;
    if (idx < Bsz * Hsz) {
        g_hA[idx] = eh[idx];
        int j = idx % Dsz;
        g_x[idx] = slot_emb[slot_p[0] * Dsz + j];
    }
}

// ---------------- K1: GEMM partials ----------------
// grid = 2 mats * 50 jtiles * 4 ksplits = 400 blocks, 96 threads.
// Thread = (tj 0..5, tb 0..15): 4b x 4j micro-tile via fma.rn.f32x2.
__global__ __launch_bounds__(96) void gemm_kernel(const float* __restrict__ Wih,
                                                  const float* __restrict__ Whh,
                                                  int t) {
    __shared__ float As[KC][68];   // [k][b], padded row 68 (16B-aligned rows)
    __shared__ float Ws[KC][28];   // [k][j], padded row 28

    int bx = blockIdx.x;
    int mat = bx / 200;
    int rem = bx % 200;
    int jt  = rem / NPART;
    int ks  = rem % NPART;
    int jbase = jt * JT;
    int kbase = ks * KC;

    const float* hin = (t & 1) ? g_hB : g_hA;
    const float* A = mat ? hin : g_x;
    const float* W = mat ? Whh : Wih;

    int tid = threadIdx.x;

    // stage A chunk transposed: As[k][b]
    for (int i = tid; i < 64 * (KC / 4); i += 96) {   // 1600
        int q = i / 64, b = i % 64;
        float4 v = *(const float4*)&A[b * 400 + kbase + 4 * q];
        As[4 * q + 0][b] = v.x;
        As[4 * q + 1][b] = v.y;
        As[4 * q + 2][b] = v.z;
        As[4 * q + 3][b] = v.w;
    }
    // stage W chunk transposed: Ws[k][j]
    for (int i = tid; i < JT * (KC / 4); i += 96) {   // 600
        int q = i / JT, j = i % JT;
        float4 v = *(const float4*)&W[(jbase + j) * 400 + kbase + 4 * q];
        Ws[4 * q + 0][j] = v.x;
        Ws[4 * q + 1][j] = v.y;
        Ws[4 * q + 2][j] = v.z;
        Ws[4 * q + 3][j] = v.w;
    }
    __syncthreads();

    int tj = tid / 16;          // 0..5
    int tb = tid % 16;          // 0..15
    int b0 = 4 * tb;
    int j0 = 4 * tj;

    unsigned long long acc[4][2];
    #pragma unroll
    for (int jj = 0; jj < 4; jj++) { acc[jj][0] = 0ULL; acc[jj][1] = 0ULL; }

    #pragma unroll 4
    for (int k = 0; k < KC; k++) {
        float4 av = *(const float4*)&As[k][b0];
        float4 wv = *(const float4*)&Ws[k][j0];
        unsigned long long a01 = pk2(av.x, av.y);
        unsigned long long a23 = pk2(av.z, av.w);
        unsigned long long w0 = pk2(wv.x, wv.x);
        unsigned long long w1 = pk2(wv.y, wv.y);
        unsigned long long w2 = pk2(wv.z, wv.z);
        unsigned long long w3 = pk2(wv.w, wv.w);
        ffma2(acc[0][0], a01, w0); ffma2(acc[0][1], a23, w0);
        ffma2(acc[1][0], a01, w1); ffma2(acc[1][1], a23, w1);
        ffma2(acc[2][0], a01, w2); ffma2(acc[2][1], a23, w2);
        ffma2(acc[3][0], a01, w3); ffma2(acc[3][1], a23, w3);
    }

    // unpack & store: 4 STG.128 (one per b row)
    float val[4][4];
    #pragma unroll
    for (int jj = 0; jj < 4; jj++) {
        float2 lo = up2(acc[jj][0]);
        float2 hi = up2(acc[jj][1]);
        val[jj][0] = lo.x; val[jj][1] = lo.y; val[jj][2] = hi.x; val[jj][3] = hi.y;
    }
    int obase = mat * 1200 + jbase + j0;
    #pragma unroll
    for (int bb = 0; bb < 4; bb++) {
        float4 o = make_float4(val[0][bb], val[1][bb], val[2][bb], val[3][bb]);
        *(float4*)&g_Gpart[ks][b0 + bb][obase] = o;
    }
}

// ---------------- K1.5: gates -> h_new ----------------
// grid 64 (b), 128 threads; tid<100 handle one float4 (4 H-elements).
__global__ __launch_bounds__(128) void gates_kernel(const float* __restrict__ bih,
                                                    const float* __restrict__ bhh,
                                                    int t) {
    int b = blockIdx.x;
    int tid = threadIdx.x;
    if (tid >= 100) return;
    const float* hin = (t & 1) ? g_hB : g_hA;
    float* hout = (t & 1) ? g_hA : g_hB;

    float4 ir = *(const float4*)&bih[4 * tid];
    float4 iz = *(const float4*)&bih[400 + 4 * tid];
    float4 in_ = *(const float4*)&bih[800 + 4 * tid];
    float4 hr = *(const float4*)&bhh[4 * tid];
    float4 hz = *(const float4*)&bhh[400 + 4 * tid];
    float4 hn = *(const float4*)&bhh[800 + 4 * tid];

    #pragma unroll
    for (int p = 0; p < NPART; p++) {
        const float* P = &g_Gpart[p][b][0];
        float4 v;
        v = *(const float4*)&P[4 * tid];        ir.x += v.x; ir.y += v.y; ir.z += v.z; ir.w += v.w;
        v = *(const float4*)&P[400 + 4 * tid];  iz.x += v.x; iz.y += v.y; iz.z += v.z; iz.w += v.w;
        v = *(const float4*)&P[800 + 4 * tid];  in_.x += v.x; in_.y += v.y; in_.z += v.z; in_.w += v.w;
        v = *(const float4*)&P[1200 + 4 * tid]; hr.x += v.x; hr.y += v.y; hr.z += v.z; hr.w += v.w;
        v = *(const float4*)&P[1600 + 4 * tid]; hz.x += v.x; hz.y += v.y; hz.z += v.z; hz.w += v.w;
        v = *(const float4*)&P[2000 + 4 * tid]; hn.x += v.x; hn.y += v.y; hn.z += v.z; hn.w += v.w;
    }

    float4 hp = *(const float4*)&hin[b * 400 + 4 * tid];
    float4 ho;
    {
        float r = 1.f / (1.f + expf(-(ir.x + hr.x)));
        float z = 1.f / (1.f + expf(-(iz.x + hz.x)));
        float n = tanhf(in_.x + r * hn.x);
        ho.x = (1.f - z) * n + z * hp.x;
    }
    {
        float r = 1.f / (1.f + expf(-(ir.y + hr.y)));
        float z = 1.f / (1.f + expf(-(iz.y + hz.y)));
        float n = tanhf(in_.y + r * hn.y);
        ho.y = (1.f - z) * n + z * hp.y;
    }
    {
        float r = 1.f / (1.f + expf(-(ir.z + hr.z)));
        float z = 1.f / (1.f + expf(-(iz.z + hz.z)));
        float n = tanhf(in_.z + r * hn.z);
        ho.z = (1.f - z) * n + z * hp.z;
    }
    {
        float r = 1.f / (1.f + expf(-(ir.w + hr.w)));
        float z = 1.f / (1.f + expf(-(iz.w + hz.w)));
        float n = tanhf(in_.w + r * hn.w);
        ho.w = (1.f - z) * n + z * hp.w;
    }
    *(float4*)&hout[b * 400 + 4 * tid] = ho;
}

// ---------------- K2: masked scores, 512 blocks (64 b x 8 s-chunks) ----------------
__global__ __launch_bounds__(256) void score_kernel(const float* __restrict__ enc,
                                                    const int* __restrict__ lens,
                                                    int t) {
    __shared__ float sh[Hsz];
    int bx = blockIdx.x;
    int b = bx & 63;
    int chunk = bx >> 6;
    int tid = threadIdx.x;
    const float* hnew = (t & 1) ? g_hA : g_hB;   // h_out of this step

    if (tid < 100)
        ((float4*)sh)[tid] = ((const float4*)(hnew + b * 400))[tid];
    __syncthreads();

    int len = lens[b];
    int warp = tid >> 5, lane = tid & 31;
    const float4* h4 = (const float4*)sh;

    #pragma unroll
    for (int i = 0; i < 8; i++) {
        int s = chunk * 64 + warp * 8 + i;
        if (s < len) {
            const float4* e = (const float4*)(enc + ((size_t)b * Ssz + s) * Hsz);
            float acc = 0.f;
            #pragma unroll 4
            for (int q = lane; q < 100; q += 32) {
                float4 a = e[q];
                float4 hv = h4[q];
                acc += a.x * hv.x; acc += a.y * hv.y;
                acc += a.z * hv.z; acc += a.w * hv.w;
            }
            #pragma unroll
            for (int off = 16; off; off >>= 1)
                acc += __shfl_xor_sync(0xFFFFFFFFu, acc, off);
            if (lane == 0) g_scores[b][s] = acc;
        } else if (lane == 0) {
            g_scores[b][s] = -INFINITY;
        }
    }
}

// ---------------- K3: softmax + scatter + pred + next-x gather ----------------
__global__ __launch_bounds__(512) void softmax_kernel(const int* __restrict__ lens,
                                                      const int* __restrict__ uttrs,
                                                      const int* __restrict__ targets,
                                                      const int* __restrict__ use_tf_p,
                                                      const float* __restrict__ embedding,
                                                      float* __restrict__ out,
                                                      int t, int write_preds) {
    __shared__ float redv[512];
    __shared__ int   redi[512];
    __shared__ int   sh_nxt;

    int b = blockIdx.x;
    int tx = threadIdx.x;

    float myv = g_scores[b][tx];
    redv[tx] = myv;
    redi[tx] = tx;
    __syncthreads();
    // first-index-tie-break max (jnp.argmax semantics)
    for (int st = 256; st > 0; st >>= 1) {
        if (tx < st) {
            float v2 = redv[tx + st];
            int   i2 = redi[tx + st];
            if (v2 > redv[tx] || (v2 == redv[tx] && i2 < redi[tx])) {
                redv[tx] = v2;
                redi[tx] = i2;
            }
        }
        __syncthreads();
    }
    float m = redv[0];
    int amax = redi[0];
    __syncthreads();

    float e = expf(myv - m);     // exp(-inf - m) = 0 for masked rows
    redv[tx] = e;
    __syncthreads();
    for (int st = 256; st > 0; st >>= 1) {
        if (tx < st) redv[tx] += redv[tx + st];
        __syncthreads();
    }
    float sum = redv[0];

    int len = lens[b];
    if (tx < len) {
        float p = e / sum;
        int v = uttrs[b * Ssz + tx];
        atomicAdd(&out[(size_t)b * Lsz * Vsz + (size_t)t * Vsz + v], p);
    }

    if (tx == 0) {
        int pred = uttrs[b * Ssz + amax];
        if (write_preds)
            out[(size_t)Bsz * Lsz * Vsz + (size_t)t * Bsz + b] = (float)pred;
        int tf = use_tf_p[0];
        sh_nxt = tf ? targets[b * Lsz + t] : pred;
    }
    __syncthreads();

    if (tx < 100) {
        ((float4*)(g_x + b * Dsz))[tx] =
            ((const float4*)(embedding + (size_t)sh_nxt * Dsz))[tx];
    }
}

// ---------------- launch ----------------
extern "C" void kernel_launch(void* const* d_in, const int* in_sizes, int n_in,
                              void* d_out, int out_size) {
    const float* eh       = (const float*)d_in[0];   // encoded_hidden (1,B,H)
    const float* enc      = (const float*)d_in[1];   // encoded_outputs (B,S,H)
    const int*   lens     = (const int*)d_in[2];     // encoded_lens (B,)
    const int*   uttrs    = (const int*)d_in[3];     // (B,S)
    const int*   targets  = (const int*)d_in[4];     // (B,L)
    const int*   slot     = (const int*)d_in[5];     // scalar
    const int*   use_tf   = (const int*)d_in[6];     // scalar
    const float* emb      = (const float*)d_in[7];   // (V,D)
    const float* slot_emb = (const float*)d_in[8];   // (NSLOTS,D)
    const float* Wih      = (const float*)d_in[9];   // (3H,D)
    const float* Whh      = (const float*)d_in[10];  // (3H,H)
    const float* bih      = (const float*)d_in[11];
    const float* bhh      = (const float*)d_in[12];
    float* out = (float*)d_out;

    cudaMemsetAsync(d_out, 0, (size_t)out_size * sizeof(float));
    init_kernel<<<50, 512>>>(eh, slot_emb, slot);

    int write_preds = out_size > Bsz * Lsz * Vsz;
    for (int t = 0; t < Lsz; t++) {
        gemm_kernel<<<400, 96>>>(Wih, Whh, t);
        gates_kernel<<<64, 128>>>(bih, bhh, t);
        score_kernel<<<512, 256>>>(enc, lens, t);
        softmax_kernel<<<64, 512>>>(lens, uttrs, targets, use_tf, emb, out, t, write_preds);
    }
}